// round 7
// baseline (speedup 1.0000x reference)
#include <cuda_runtime.h>
#include <cuda_bf16.h>

// Problem constants
#define BATCH 16
#define SEQ   4096
#define HDIM  1024
#define HN    16      // heads
#define HD    64      // head dim

// ---------------------------------------------------------------------------
// Scratch (device globals: no allocation allowed)
// ---------------------------------------------------------------------------
__device__ float g_q[BATCH * HDIM];          // q = query @ Wq^T + bq
__device__ float g_w[BATCH * HN * HDIM];     // w[b,h,:] = (1/32) Wk_h^T q_h
__device__ float g_c[BATCH * HN];            // (1/32) q_h . bk_h
__device__ float g_u[BATCH * HN * HDIM];     // u[b,h,:] = sum_s att * value_row
__device__ float g_A[BATCH * HN];            // A[b,h]   = sum_s att
__device__ float g_o1[BATCH * HDIM];         // out before final projection

// ---------------------------------------------------------------------------
// helpers
// ---------------------------------------------------------------------------
__device__ __forceinline__ void fma2(unsigned long long &d,
                                     unsigned long long a,
                                     unsigned long long b) {
    asm("fma.rn.f32x2 %0, %1, %2, %0;" : "+l"(d) : "l"(a), "l"(b));
}
__device__ __forceinline__ float2 unpack2(unsigned long long v) {
    float2 f;
    asm("mov.b64 {%0, %1}, %2;" : "=f"(f.x), "=f"(f.y) : "l"(v));
    return f;
}
__device__ __forceinline__ unsigned long long pack2(float a, float b) {
    unsigned long long r;
    asm("mov.b64 %0, {%1, %2};" : "=l"(r) : "f"(a), "f"(b));
    return r;
}
__device__ __forceinline__ unsigned long long pack_dup(float a) {
    unsigned long long r;
    asm("mov.b64 %0, {%1, %1};" : "=l"(r) : "f"(a));
    return r;
}
__device__ __forceinline__ unsigned smem_u32(const void* p) {
    unsigned a;
    asm("{ .reg .u64 t; cvta.to.shared.u64 t, %1; cvt.u32.u64 %0, t; }"
        : "=r"(a) : "l"(p));
    return a;
}
__device__ __forceinline__ void mbar_init(unsigned mbar, unsigned count) {
    asm volatile("mbarrier.init.shared::cta.b64 [%0], %1;"
                 :: "r"(mbar), "r"(count) : "memory");
}
__device__ __forceinline__ void mbar_expect_tx(unsigned mbar, unsigned bytes) {
    asm volatile("mbarrier.arrive.expect_tx.shared::cta.b64 _, [%0], %1;"
                 :: "r"(mbar), "r"(bytes) : "memory");
}
__device__ __forceinline__ void mbar_wait(unsigned mbar, unsigned parity) {
    asm volatile(
        "{\n\t"
        ".reg .pred P;\n\t"
        "WAIT_%=:\n\t"
        "mbarrier.try_wait.parity.acquire.cta.shared::cta.b64 P, [%0], %1;\n\t"
        "@!P bra WAIT_%=;\n\t"
        "}"
        :: "r"(mbar), "r"(parity) : "memory");
}
// 1D bulk TMA: global -> shared::cta, completion via mbarrier tx bytes
__device__ __forceinline__ void tma_bulk_g2s(unsigned dst, const void* src,
                                             unsigned bytes, unsigned mbar) {
    asm volatile(
        "cp.async.bulk.shared::cta.global.mbarrier::complete_tx::bytes "
        "[%0], [%1], %2, [%3];"
        :: "r"(dst), "l"(src), "r"(bytes), "r"(mbar) : "memory");
}
__device__ __forceinline__ void bar_score() {   // named barrier: score warps only
    asm volatile("bar.sync 1, 256;" ::: "memory");
}

// ---------------------------------------------------------------------------
// K1: q[b,i] = query[b,:] . Wq[i,:] + bq[i]   (warp per output)
// ---------------------------------------------------------------------------
__global__ void k1_q(const float* __restrict__ query,
                     const float* __restrict__ Wq,
                     const float* __restrict__ bq) {
    int gw   = (blockIdx.x * blockDim.x + threadIdx.x) >> 5;
    int lane = threadIdx.x & 31;
    if (gw >= BATCH * HDIM) return;
    int b = gw >> 10, i = gw & 1023;
    const float4* qr = (const float4*)(query + b * HDIM);
    const float4* wr = (const float4*)(Wq + (size_t)i * HDIM);
    float acc = 0.f;
#pragma unroll
    for (int t = 0; t < 8; t++) {
        float4 a = qr[t * 32 + lane];
        float4 w = wr[t * 32 + lane];
        acc += a.x * w.x + a.y * w.y + a.z * w.z + a.w * w.w;
    }
#pragma unroll
    for (int o = 16; o > 0; o >>= 1) acc += __shfl_xor_sync(~0u, acc, o);
    if (lane == 0) g_q[gw] = acc + bq[i];
}

// ---------------------------------------------------------------------------
// K2: w[b,h,j] = (1/32) sum_d q[b,h*64+d] * Wk[h*64+d, j];  also zeros g_u/g_A
// ---------------------------------------------------------------------------
__global__ void k2_w(const float* __restrict__ Wk,
                     const float* __restrict__ bk) {
    int h = blockIdx.x >> 4;
    int b = blockIdx.x & 15;
    int tid = threadIdx.x;

    int gtid = blockIdx.x * 256 + tid;
    ((float4*)g_u)[gtid] = make_float4(0.f, 0.f, 0.f, 0.f);
    if (gtid < BATCH * HN) g_A[gtid] = 0.f;

    __shared__ float qh[HD];
    if (tid < HD) qh[tid] = g_q[b * HDIM + h * HD + tid];
    __syncthreads();

    float4 acc = make_float4(0.f, 0.f, 0.f, 0.f);
    const float4* wk = (const float4*)(Wk + (size_t)(h * HD) * HDIM) + tid;
#pragma unroll 8
    for (int d = 0; d < HD; d++) {
        float4 v = wk[d * 256];
        float  s = qh[d];
        acc.x += s * v.x; acc.y += s * v.y; acc.z += s * v.z; acc.w += s * v.w;
    }
    const float scale = 0.03125f;  // 1/sqrt(1024)
    acc.x *= scale; acc.y *= scale; acc.z *= scale; acc.w *= scale;
    ((float4*)(g_w + (b * HN + h) * HDIM))[tid] = acc;

    if (tid == 0) {
        float cc = 0.f;
        for (int d = 0; d < HD; d++) cc += qh[d] * bk[h * HD + d];
        g_c[b * HN + h] = cc * scale;
    }
}

// ---------------------------------------------------------------------------
// K3 fused v3: warp-specialized scores+softmax+accumulate, streams via
// 1D bulk TMA + mbarriers (key 2-slot ring, value 3-slot ring).
//  grid (8 chunks of 512 rows, 16 b) = 128 CTAs (single wave), 512 threads,
//  1 CTA/SM, ~166KB smem. Warps 0-7 = SCORE (w register-resident), warps
//  8-15 = ACCUM (u register-resident). 32KB tile moves with ONE bulk op per
//  stage per stream (was 2048 cp.async each) — removes the LDGSTS issue wall.
// ---------------------------------------------------------------------------
#define FK3_STAGES 64            // 512 rows / 8
#define STAGE_BYTES 32768u       // 8 rows x 1024 floats x 4B
__global__ __launch_bounds__(512, 1)
void k3_fused(const float* __restrict__ key,
              const float* __restrict__ value) {
    extern __shared__ float smem_raw[];
    float* kbuf = smem_raw;                                    // 2 x 8192
    float* vbuf = kbuf + 16384;                                // 3 x 8192
    float* part = vbuf + 24576;                                // 1024
    unsigned long long* att_pk = (unsigned long long*)(part + 1024);  // 2 x 128
    float* c_s = (float*)(att_pk + 256);                       // 16
    unsigned long long* mbars = (unsigned long long*)(c_s + 16); // kmbar[2], vmbar[3]

    const int b     = blockIdx.y;
    const int chunk = blockIdx.x;
    const int tid   = threadIdx.x;
    const int wid   = tid >> 5;
    const int lane  = tid & 31;
    const int row0  = chunk * 512;

    const unsigned kbuf_addr = smem_u32(kbuf);
    const unsigned vbuf_addr = smem_u32(vbuf);
    const unsigned kmbar = smem_u32(mbars);          // +0, +8
    const unsigned vmbar = kmbar + 16;               // +0, +8, +16

    if (tid == 0) {
#pragma unroll
        for (int i = 0; i < 5; i++) mbar_init(kmbar + 8 * i, 1);
    }
    if (tid < HN) c_s[tid] = g_c[b * HN + tid];
    __syncthreads();   // mbars + c_s visible

    if (wid < 8) {
        // ================= SCORE role (threads 0..255) =================
        const int h     = lane & 15;
        const int jhalf = lane >> 4;
        const int slice_off = wid * 128 + jhalf * 64;

        unsigned long long wreg[32];
        {
            const float4* wsrc = (const float4*)(g_w + (size_t)(b * HN + h) * HDIM + slice_off);
#pragma unroll
            for (int t = 0; t < 16; t++) {
                float4 f = wsrc[t];
                wreg[2 * t + 0] = pack2(f.x, f.y);
                wreg[2 * t + 1] = pack2(f.z, f.w);
            }
        }

        const float* keyb = key + (size_t)b * SEQ * HDIM;

        // prologue: bulk-load key stages 0 and 1
        if (tid == 0) {
#pragma unroll
            for (int s = 0; s < 2; s++) {
                mbar_expect_tx(kmbar + 8 * s, STAGE_BYTES);
                tma_bulk_g2s(kbuf_addr + s * STAGE_BYTES,
                             keyb + (size_t)(row0 + s * 8) * HDIM,
                             STAGE_BYTES, kmbar + 8 * s);
            }
        }

        for (int s = 0; s <= FK3_STAGES; s++) {
            if (s < FK3_STAGES) {
                const int buf = s & 1;
                mbar_wait(kmbar + 8 * buf, (s >> 1) & 1);

                // scores for 8 rows from smem broadcast
                const float4* kb = (const float4*)(kbuf + buf * 8192) + (slice_off >> 2);
                float* pdst = part + wid * 128 + h;
#pragma unroll
                for (int r = 0; r < 8; r++) {
                    unsigned long long acc = 0ULL;
                    const float4* krow = kb + r * 256;
#pragma unroll
                    for (int t = 0; t < 16; t++) {
                        float4 kv = krow[t];
                        fma2(acc, pack2(kv.x, kv.y), wreg[2 * t + 0]);
                        fma2(acc, pack2(kv.z, kv.w), wreg[2 * t + 1]);
                    }
                    float2 fa = unpack2(acc);
                    float f = fa.x + fa.y;
                    f += __shfl_xor_sync(~0u, f, 16);
                    if (lane < 16) pdst[r * 16] = f;
                }
                bar_score();   // all score warps done reading kbuf[buf]; part visible

                // refill kbuf[buf] with key stage s+2 (single bulk op)
                if (tid == 0 && s + 2 < FK3_STAGES) {
                    mbar_expect_tx(kmbar + 8 * buf, STAGE_BYTES);
                    tma_bulk_g2s(kbuf_addr + buf * STAGE_BYTES,
                                 keyb + (size_t)(row0 + (s + 2) * 8) * HDIM,
                                 STAGE_BYTES, kmbar + 8 * buf);
                }

                // softmax: thread t<128 = (row t>>4, head t&15)
                if (tid < 128) {
                    const int r = tid >> 4, hh = tid & 15;
                    const float* psrc = part + r * 16 + hh;
                    float sc = c_s[hh];
#pragma unroll
                    for (int w8 = 0; w8 < 8; w8++) sc += psrc[w8 * 128];
                    float m = sc;
#pragma unroll
                    for (int o = 8; o > 0; o >>= 1) m = fmaxf(m, __shfl_xor_sync(~0u, m, o));
                    float e = __expf(sc - m);
                    float sum = e;
#pragma unroll
                    for (int o = 8; o > 0; o >>= 1) sum += __shfl_xor_sync(~0u, sum, o);
                    att_pk[buf * 128 + tid] = pack_dup(__fdividef(e, sum));
                }
            }
            __syncthreads();
        }
    } else {
        // ================= ACCUM role (threads 256..511) =================
        const int aw  = wid - 8;
        const int j0  = aw * 128 + lane * 4;
        const float* valb = value + (size_t)b * SEQ * HDIM;

        unsigned long long u2[32];
#pragma unroll
        for (int i = 0; i < 32; i++) u2[i] = 0ULL;
        float a_loc = 0.f;

        // prologue: bulk-load value stage 0 into slot 0
        if (tid == 256) {
            mbar_expect_tx(vmbar, STAGE_BYTES);
            tma_bulk_g2s(vbuf_addr, valb + (size_t)row0 * HDIM, STAGE_BYTES, vmbar);
        }

        for (int s = 0; s <= FK3_STAGES; s++) {
            // prefetch value[s+1] into slot (s+1)%3 (slot free: last used at s-2)
            if (tid == 256 && s + 1 < FK3_STAGES) {
                const int slot = (s + 1) % 3;
                mbar_expect_tx(vmbar + 8 * slot, STAGE_BYTES);
                tma_bulk_g2s(vbuf_addr + slot * STAGE_BYTES,
                             valb + (size_t)(row0 + (s + 1) * 8) * HDIM,
                             STAGE_BYTES, vmbar + 8 * slot);
            }

            if (s >= 1) {
                const int t = s - 1;
                mbar_wait(vmbar + 8 * (t % 3), (t / 3) & 1);

                const float* vb = vbuf + (t % 3) * 8192 + j0;
                const ulonglong2* ap2 = (const ulonglong2*)(att_pk + (t & 1) * 128);

                ulonglong2 vv[8];
#pragma unroll
                for (int r = 0; r < 8; r++)
                    vv[r] = *(const ulonglong2*)(vb + r * 1024);
#pragma unroll
                for (int r = 0; r < 8; r++) {
#pragma unroll
                    for (int hp = 0; hp < 8; hp++) {
                        ulonglong2 a = ap2[r * 8 + hp];   // heads 2hp, 2hp+1
                        fma2(u2[4 * hp + 0], a.x, vv[r].x);
                        fma2(u2[4 * hp + 1], a.x, vv[r].y);
                        fma2(u2[4 * hp + 2], a.y, vv[r].x);
                        fma2(u2[4 * hp + 3], a.y, vv[r].y);
                    }
                }
                if (aw == 0 && lane < 16) {
                    const float* af = (const float*)(att_pk + (t & 1) * 128);
#pragma unroll
                    for (int r = 0; r < 8; r++)
                        a_loc += af[(r * 16 + lane) * 2];
                }
            }
            __syncthreads();
        }

        // flush u partials (8 CTAs per b contend per address — fine)
        float* ubase = g_u + (b * HN) * HDIM + j0;
#pragma unroll
        for (int hh = 0; hh < 16; hh++) {
            float2 lo = unpack2(u2[2 * hh + 0]);
            float2 hi = unpack2(u2[2 * hh + 1]);
            atomicAdd(ubase + (hh << 10) + 0, lo.x);
            atomicAdd(ubase + (hh << 10) + 1, lo.y);
            atomicAdd(ubase + (hh << 10) + 2, hi.x);
            atomicAdd(ubase + (hh << 10) + 3, hi.y);
        }
        if (aw == 0 && lane < 16) atomicAdd(&g_A[b * HN + lane], a_loc);
    }
}

// ---------------------------------------------------------------------------
// K4: o1[b,j] = Wv[j,:] . u[b, j/64, :] + bv[j] * A[b, j/64]   warp per (j,b)
// ---------------------------------------------------------------------------
__global__ void k4_out(const float* __restrict__ Wv,
                       const float* __restrict__ bv) {
    int gw   = (blockIdx.x * blockDim.x + threadIdx.x) >> 5;
    int lane = threadIdx.x & 31;
    if (gw >= HDIM * BATCH) return;
    int b = gw & 15, j = gw >> 4, h = j >> 6;
    const float4* wr = (const float4*)(Wv + (size_t)j * HDIM);
    const float4* ur = (const float4*)(g_u + (b * HN + h) * HDIM);
    float acc = 0.f;
#pragma unroll
    for (int t = 0; t < 8; t++) {
        float4 w = wr[t * 32 + lane];
        float4 u = ur[t * 32 + lane];
        acc += w.x * u.x + w.y * u.y + w.z * u.z + w.w * u.w;
    }
#pragma unroll
    for (int o = 16; o > 0; o >>= 1) acc += __shfl_xor_sync(~0u, acc, o);
    if (lane == 0) g_o1[b * HDIM + j] = acc + bv[j] * g_A[b * HN + h];
}

// ---------------------------------------------------------------------------
// K5: res[b,i] = Wf[i,:] . o1[b,:] + bf[i]   warp per (i,b)
// ---------------------------------------------------------------------------
__global__ void k5_final(const float* __restrict__ Wf,
                         const float* __restrict__ bf,
                         float* __restrict__ res) {
    int gw   = (blockIdx.x * blockDim.x + threadIdx.x) >> 5;
    int lane = threadIdx.x & 31;
    if (gw >= HDIM * BATCH) return;
    int b = gw & 15, i = gw >> 4;
    const float4* wr = (const float4*)(Wf + (size_t)i * HDIM);
    const float4* orow = (const float4*)(g_o1 + b * HDIM);
    float acc = 0.f;
#pragma unroll
    for (int t = 0; t < 8; t++) {
        float4 w = wr[t * 32 + lane];
        float4 o = orow[t * 32 + lane];
        acc += w.x * o.x + w.y * o.y + w.z * o.z + w.w * o.w;
    }
#pragma unroll
    for (int o = 16; o > 0; o >>= 1) acc += __shfl_xor_sync(~0u, acc, o);
    if (lane == 0) res[b * HDIM + i] = acc + bf[i];
}

// ---------------------------------------------------------------------------
// launch
// ---------------------------------------------------------------------------
extern "C" void kernel_launch(void* const* d_in, const int* in_sizes, int n_in,
                              void* d_out, int out_size) {
    const float* query = (const float*)d_in[0];
    const float* key_  = (const float*)d_in[1];
    const float* value = (const float*)d_in[2];
    const float* Wq    = (const float*)d_in[3];
    const float* bq    = (const float*)d_in[4];
    const float* Wk    = (const float*)d_in[5];
    const float* bk    = (const float*)d_in[6];
    const float* Wv    = (const float*)d_in[7];
    const float* bv    = (const float*)d_in[8];
    const float* Wf    = (const float*)d_in[9];
    const float* bf    = (const float*)d_in[10];
    float* out = (float*)d_out;

    // kbuf 16384 + vbuf 24576 + part 1024 + att_pk 512 + c 16 + mbars 12 floats
    const int k3_smem = (16384 + 24576 + 1024 + 512 + 16 + 12) * 4;   // 170096 B
    static bool attr_set = false;
    if (!attr_set) {
        cudaFuncSetAttribute(k3_fused, cudaFuncAttributeMaxDynamicSharedMemorySize, k3_smem);
        attr_set = true;
    }

    k1_q<<<(BATCH * HDIM * 32 + 255) / 256, 256>>>(query, Wq, bq);
    k2_w<<<HN * BATCH, 256>>>(Wk, bk);
    {
        dim3 grid(SEQ / 512, BATCH);   // 8 x 16 = 128 CTAs, single wave
        k3_fused<<<grid, 512, k3_smem>>>(key_, value);
    }
    k4_out<<<(HDIM * BATCH * 32 + 255) / 256, 256>>>(Wv, bv);
    k5_final<<<(HDIM * BATCH * 32 + 255) / 256, 256>>>(Wf, bf, out);
}

// round 8
// speedup vs baseline: 1.1722x; 1.1722x over previous
#include <cuda_runtime.h>
#include <cuda_bf16.h>

// Problem constants
#define BATCH 16
#define SEQ   4096
#define HDIM  1024
#define HN    16      // heads
#define HD    64      // head dim

// ---------------------------------------------------------------------------
// Scratch (device globals: no allocation allowed)
// ---------------------------------------------------------------------------
__device__ float g_q[BATCH * HDIM];          // q = query @ Wq^T + bq
__device__ float g_w[BATCH * HN * HDIM];     // w[b,h,:] = (1/32) Wk_h^T q_h
__device__ float g_c[BATCH * HN];            // (1/32) q_h . bk_h
__device__ float g_u[BATCH * HN * HDIM];     // u[b,h,:] = sum_s att * value_row
__device__ float g_A[BATCH * HN];            // A[b,h]   = sum_s att
__device__ float g_o1[BATCH * HDIM];         // out before final projection

// ---------------------------------------------------------------------------
// f32x2 helpers (packed FFMA2)
// ---------------------------------------------------------------------------
__device__ __forceinline__ void fma2(unsigned long long &d,
                                     unsigned long long a,
                                     unsigned long long b) {
    asm("fma.rn.f32x2 %0, %1, %2, %0;" : "+l"(d) : "l"(a), "l"(b));
}
__device__ __forceinline__ float2 unpack2(unsigned long long v) {
    float2 f;
    asm("mov.b64 {%0, %1}, %2;" : "=f"(f.x), "=f"(f.y) : "l"(v));
    return f;
}
__device__ __forceinline__ unsigned long long pack2(float a, float b) {
    unsigned long long r;
    asm("mov.b64 %0, {%1, %2};" : "=l"(r) : "f"(a), "f"(b));
    return r;
}
__device__ __forceinline__ unsigned long long pack_dup(float a) {
    unsigned long long r;
    asm("mov.b64 %0, {%1, %1};" : "=l"(r) : "f"(a));
    return r;
}
__device__ __forceinline__ unsigned smem_u32(const void* p) {
    unsigned a;
    asm("{ .reg .u64 t; cvta.to.shared.u64 t, %1; cvt.u32.u64 %0, t; }"
        : "=r"(a) : "l"(p));
    return a;
}
__device__ __forceinline__ void cp_async16(unsigned dst, const void* src) {
    asm volatile("cp.async.cg.shared.global [%0], [%1], 16;"
                 :: "r"(dst), "l"(src) : "memory");
}
__device__ __forceinline__ void cp_commit() {
    asm volatile("cp.async.commit_group;" ::: "memory");
}
__device__ __forceinline__ void cp_wait1() {
    asm volatile("cp.async.wait_group 1;" ::: "memory");
}
__device__ __forceinline__ void cp_wait2() {
    asm volatile("cp.async.wait_group 2;" ::: "memory");
}
__device__ __forceinline__ void bar_score() {   // named barrier: score warps only
    asm volatile("bar.sync 1, 256;" ::: "memory");
}

// ---------------------------------------------------------------------------
// K1: q[b,i] = query[b,:] . Wq[i,:] + bq[i]   (warp per output)
// ---------------------------------------------------------------------------
__global__ void k1_q(const float* __restrict__ query,
                     const float* __restrict__ Wq,
                     const float* __restrict__ bq) {
    int gw   = (blockIdx.x * blockDim.x + threadIdx.x) >> 5;
    int lane = threadIdx.x & 31;
    if (gw >= BATCH * HDIM) return;
    int b = gw >> 10, i = gw & 1023;
    const float4* qr = (const float4*)(query + b * HDIM);
    const float4* wr = (const float4*)(Wq + (size_t)i * HDIM);
    float acc = 0.f;
#pragma unroll
    for (int t = 0; t < 8; t++) {
        float4 a = qr[t * 32 + lane];
        float4 w = wr[t * 32 + lane];
        acc += a.x * w.x + a.y * w.y + a.z * w.z + a.w * w.w;
    }
#pragma unroll
    for (int o = 16; o > 0; o >>= 1) acc += __shfl_xor_sync(~0u, acc, o);
    if (lane == 0) g_q[gw] = acc + bq[i];
}

// ---------------------------------------------------------------------------
// K2: w[b,h,j] = (1/32) sum_d q[b,h*64+d] * Wk[h*64+d, j];  also zeros g_u/g_A
// ---------------------------------------------------------------------------
__global__ void k2_w(const float* __restrict__ Wk,
                     const float* __restrict__ bk) {
    int h = blockIdx.x >> 4;
    int b = blockIdx.x & 15;
    int tid = threadIdx.x;

    int gtid = blockIdx.x * 256 + tid;
    ((float4*)g_u)[gtid] = make_float4(0.f, 0.f, 0.f, 0.f);
    if (gtid < BATCH * HN) g_A[gtid] = 0.f;

    __shared__ float qh[HD];
    if (tid < HD) qh[tid] = g_q[b * HDIM + h * HD + tid];
    __syncthreads();

    float4 acc = make_float4(0.f, 0.f, 0.f, 0.f);
    const float4* wk = (const float4*)(Wk + (size_t)(h * HD) * HDIM) + tid;
#pragma unroll 8
    for (int d = 0; d < HD; d++) {
        float4 v = wk[d * 256];
        float  s = qh[d];
        acc.x += s * v.x; acc.y += s * v.y; acc.z += s * v.z; acc.w += s * v.w;
    }
    const float scale = 0.03125f;  // 1/sqrt(1024)
    acc.x *= scale; acc.y *= scale; acc.z *= scale; acc.w *= scale;
    ((float4*)(g_w + (b * HN + h) * HDIM))[tid] = acc;

    if (tid == 0) {
        float cc = 0.f;
        for (int d = 0; d < HD; d++) cc += qh[d] * bk[h * HD + d];
        g_c[b * HN + h] = cc * scale;
    }
}

// ---------------------------------------------------------------------------
// K3 fused v4: warp-specialized scores+softmax+accumulate, cp.async streams
// (key double-buffered, value triple-buffered). Score lane layout re-tiled:
// lane = (head-pair hg = lane&7, j-quarter jq = lane>>3) holds w for 2 heads
// x 32 j -> 8 LDS.128 per row (was 16) and 4 independent fma2 accumulator
// chains (dep depth 32 cyc/row, was 128).
// ---------------------------------------------------------------------------
#define FK3_STAGES 64            // 512 rows / 8
__global__ __launch_bounds__(512, 1)
void k3_fused(const float* __restrict__ key,
              const float* __restrict__ value) {
    extern __shared__ float smem_raw[];
    float* kbuf = smem_raw;                                    // 2 x 8192
    float* vbuf = kbuf + 16384;                                // 3 x 8192
    float* part = vbuf + 24576;                                // 1024
    unsigned long long* att_pk = (unsigned long long*)(part + 1024);  // 2 x 128
    float* c_s = (float*)(att_pk + 256);                       // 16

    const int b     = blockIdx.y;
    const int chunk = blockIdx.x;
    const int tid   = threadIdx.x;
    const int wid   = tid >> 5;
    const int lane  = tid & 31;
    const int row0  = chunk * 512;

    if (tid < HN) c_s[tid] = g_c[b * HN + tid];

    if (wid < 8) {
        // ================= SCORE role (threads 0..255) =================
        const int hg = lane & 7;          // head pair: heads 2hg, 2hg+1
        const int jq = lane >> 3;         // j quarter: 32 floats
        const int joff = wid * 128 + jq * 32;

        // w fragments: wreg[0..15] = head 2hg (16 f32x2), wreg[16..31] = head 2hg+1
        unsigned long long wreg[32];
        {
            const float4* w0 = (const float4*)(g_w + (size_t)(b * HN + 2 * hg) * HDIM + joff);
            const float4* w1 = (const float4*)(g_w + (size_t)(b * HN + 2 * hg + 1) * HDIM + joff);
#pragma unroll
            for (int t = 0; t < 8; t++) {
                float4 f = w0[t];
                wreg[2 * t + 0] = pack2(f.x, f.y);
                wreg[2 * t + 1] = pack2(f.z, f.w);
                f = w1[t];
                wreg[16 + 2 * t + 0] = pack2(f.x, f.y);
                wreg[16 + 2 * t + 1] = pack2(f.z, f.w);
            }
        }

        const float* keyb = key + (size_t)b * SEQ * HDIM;
        const unsigned kbuf_addr = smem_u32(kbuf);

        // prologue: prefetch key stages 0 and 1
#pragma unroll
        for (int s = 0; s < 2; s++) {
            const float* src = keyb + (size_t)(row0 + s * 8) * HDIM;
#pragma unroll
            for (int c = 0; c < 8; c++)
                cp_async16(kbuf_addr + (s * 8192 + c * 1024 + tid * 4) * 4,
                           src + c * 1024 + tid * 4);
            cp_commit();
        }

        for (int s = 0; s <= FK3_STAGES; s++) {
            if (s < FK3_STAGES) {
                const int buf = s & 1;
                cp_wait1();
                bar_score();

                // scores for 8 rows; per row 8 LDS.128 + 4 indep fma2 chains
                const float4* kb = (const float4*)(kbuf + buf * 8192) + (joff >> 2);
                float2* pdst2 = (float2*)(part + wid * 128);
#pragma unroll
                for (int r = 0; r < 8; r++) {
                    const float4* krow = kb + r * 256;
                    unsigned long long a00 = 0ULL, a01 = 0ULL, a10 = 0ULL, a11 = 0ULL;
#pragma unroll
                    for (int half = 0; half < 2; half++) {
                        float4 kv[4];
#pragma unroll
                        for (int t = 0; t < 4; t++) kv[t] = krow[half * 4 + t];
#pragma unroll
                        for (int t = 0; t < 4; t++) {
                            const int ti = half * 4 + t;
                            unsigned long long p0 = pack2(kv[t].x, kv[t].y);
                            unsigned long long p1 = pack2(kv[t].z, kv[t].w);
                            fma2(a00, p0, wreg[2 * ti + 0]);
                            fma2(a01, p1, wreg[2 * ti + 1]);
                            fma2(a10, p0, wreg[16 + 2 * ti + 0]);
                            fma2(a11, p1, wreg[16 + 2 * ti + 1]);
                        }
                    }
                    float2 x0 = unpack2(a00), y0 = unpack2(a01);
                    float f0 = (x0.x + x0.y) + (y0.x + y0.y);
                    float2 x1 = unpack2(a10), y1 = unpack2(a11);
                    float f1 = (x1.x + x1.y) + (y1.x + y1.y);
                    // reduce over 4 j-quarters (lanes differing in bits 3,4)
                    f0 += __shfl_xor_sync(~0u, f0, 8);
                    f1 += __shfl_xor_sync(~0u, f1, 8);
                    f0 += __shfl_xor_sync(~0u, f0, 16);
                    f1 += __shfl_xor_sync(~0u, f1, 16);
                    if (lane < 8)
                        pdst2[r * 8 + hg] = make_float2(f0, f1);  // part[wid*128 + r*16 + 2hg]
                }
                bar_score();

                // refill kbuf[buf] with key stage s+2
                if (s + 2 < FK3_STAGES) {
                    const float* src = keyb + (size_t)(row0 + (s + 2) * 8) * HDIM;
#pragma unroll
                    for (int c = 0; c < 8; c++)
                        cp_async16(kbuf_addr + (buf * 8192 + c * 1024 + tid * 4) * 4,
                                   src + c * 1024 + tid * 4);
                }
                cp_commit();

                // softmax: thread t<128 = (row t>>4, head t&15)
                if (tid < 128) {
                    const int r = tid >> 4, hh = tid & 15;
                    const float* psrc = part + r * 16 + hh;
                    float sc = c_s[hh];
#pragma unroll
                    for (int w8 = 0; w8 < 8; w8++) sc += psrc[w8 * 128];
                    float m = sc;
#pragma unroll
                    for (int o = 8; o > 0; o >>= 1) m = fmaxf(m, __shfl_xor_sync(~0u, m, o));
                    float e = __expf(sc - m);
                    float sum = e;
#pragma unroll
                    for (int o = 8; o > 0; o >>= 1) sum += __shfl_xor_sync(~0u, sum, o);
                    att_pk[buf * 128 + tid] = pack_dup(__fdividef(e, sum));
                }
            }
            __syncthreads();
        }
    } else {
        // ================= ACCUM role (threads 256..511) =================
        const int at  = tid - 256;              // 0..255
        const int aw  = wid - 8;
        const int j0  = aw * 128 + lane * 4;
        const float* valb = value + (size_t)b * SEQ * HDIM;
        const unsigned vbuf_addr = smem_u32(vbuf);

        unsigned long long u2[32];
#pragma unroll
        for (int i = 0; i < 32; i++) u2[i] = 0ULL;
        float a_loc = 0.f;

        // prologue: prefetch value stage 0 into slot 0
        {
            const float* src = valb + (size_t)row0 * HDIM;
#pragma unroll
            for (int c = 0; c < 8; c++)
                cp_async16(vbuf_addr + (c * 1024 + at * 4) * 4,
                           src + c * 1024 + at * 4);
            cp_commit();
        }

        for (int s = 0; s <= FK3_STAGES; s++) {
            // prefetch value[s+1] into slot (s+1)%3
            if (s + 1 < FK3_STAGES) {
                const int slot = (s + 1) % 3;
                const float* src = valb + (size_t)(row0 + (s + 1) * 8) * HDIM;
#pragma unroll
                for (int c = 0; c < 8; c++)
                    cp_async16(vbuf_addr + (slot * 8192 + c * 1024 + at * 4) * 4,
                               src + c * 1024 + at * 4);
            }
            cp_commit();

            if (s >= 1) {
                const int t = s - 1;
                cp_wait2();   // value[t] resident (groups t+1, t+2 may pend)

                const float* vb = vbuf + (t % 3) * 8192 + j0;
                const ulonglong2* ap2 = (const ulonglong2*)(att_pk + (t & 1) * 128);

                ulonglong2 vv[8];
#pragma unroll
                for (int r = 0; r < 8; r++)
                    vv[r] = *(const ulonglong2*)(vb + r * 1024);
#pragma unroll
                for (int r = 0; r < 8; r++) {
#pragma unroll
                    for (int hp = 0; hp < 8; hp++) {
                        ulonglong2 a = ap2[r * 8 + hp];   // heads 2hp, 2hp+1
                        fma2(u2[4 * hp + 0], a.x, vv[r].x);
                        fma2(u2[4 * hp + 1], a.x, vv[r].y);
                        fma2(u2[4 * hp + 2], a.y, vv[r].x);
                        fma2(u2[4 * hp + 3], a.y, vv[r].y);
                    }
                }
                if (aw == 0 && lane < 16) {
                    const float* af = (const float*)(att_pk + (t & 1) * 128);
#pragma unroll
                    for (int r = 0; r < 8; r++)
                        a_loc += af[(r * 16 + lane) * 2];
                }
            }
            __syncthreads();
        }

        // flush u partials (8 CTAs per b contend per address — fine)
        float* ubase = g_u + (b * HN) * HDIM + j0;
#pragma unroll
        for (int hh = 0; hh < 16; hh++) {
            float2 lo = unpack2(u2[2 * hh + 0]);
            float2 hi = unpack2(u2[2 * hh + 1]);
            atomicAdd(ubase + (hh << 10) + 0, lo.x);
            atomicAdd(ubase + (hh << 10) + 1, lo.y);
            atomicAdd(ubase + (hh << 10) + 2, hi.x);
            atomicAdd(ubase + (hh << 10) + 3, hi.y);
        }
        if (aw == 0 && lane < 16) atomicAdd(&g_A[b * HN + lane], a_loc);
    }
}

// ---------------------------------------------------------------------------
// K4: o1[b,j] = Wv[j,:] . u[b, j/64, :] + bv[j] * A[b, j/64]   warp per (j,b)
// ---------------------------------------------------------------------------
__global__ void k4_out(const float* __restrict__ Wv,
                       const float* __restrict__ bv) {
    int gw   = (blockIdx.x * blockDim.x + threadIdx.x) >> 5;
    int lane = threadIdx.x & 31;
    if (gw >= HDIM * BATCH) return;
    int b = gw & 15, j = gw >> 4, h = j >> 6;
    const float4* wr = (const float4*)(Wv + (size_t)j * HDIM);
    const float4* ur = (const float4*)(g_u + (b * HN + h) * HDIM);
    float acc = 0.f;
#pragma unroll
    for (int t = 0; t < 8; t++) {
        float4 w = wr[t * 32 + lane];
        float4 u = ur[t * 32 + lane];
        acc += w.x * u.x + w.y * u.y + w.z * u.z + w.w * u.w;
    }
#pragma unroll
    for (int o = 16; o > 0; o >>= 1) acc += __shfl_xor_sync(~0u, acc, o);
    if (lane == 0) g_o1[b * HDIM + j] = acc + bv[j] * g_A[b * HN + h];
}

// ---------------------------------------------------------------------------
// K5: res[b,i] = Wf[i,:] . o1[b,:] + bf[i]   warp per (i,b)
// ---------------------------------------------------------------------------
__global__ void k5_final(const float* __restrict__ Wf,
                         const float* __restrict__ bf,
                         float* __restrict__ res) {
    int gw   = (blockIdx.x * blockDim.x + threadIdx.x) >> 5;
    int lane = threadIdx.x & 31;
    if (gw >= HDIM * BATCH) return;
    int b = gw & 15, i = gw >> 4;
    const float4* wr = (const float4*)(Wf + (size_t)i * HDIM);
    const float4* orow = (const float4*)(g_o1 + b * HDIM);
    float acc = 0.f;
#pragma unroll
    for (int t = 0; t < 8; t++) {
        float4 w = wr[t * 32 + lane];
        float4 o = orow[t * 32 + lane];
        acc += w.x * o.x + w.y * o.y + w.z * o.z + w.w * o.w;
    }
#pragma unroll
    for (int o = 16; o > 0; o >>= 1) acc += __shfl_xor_sync(~0u, acc, o);
    if (lane == 0) res[b * HDIM + i] = acc + bf[i];
}

// ---------------------------------------------------------------------------
// launch
// ---------------------------------------------------------------------------
extern "C" void kernel_launch(void* const* d_in, const int* in_sizes, int n_in,
                              void* d_out, int out_size) {
    const float* query = (const float*)d_in[0];
    const float* key_  = (const float*)d_in[1];
    const float* value = (const float*)d_in[2];
    const float* Wq    = (const float*)d_in[3];
    const float* bq    = (const float*)d_in[4];
    const float* Wk    = (const float*)d_in[5];
    const float* bk    = (const float*)d_in[6];
    const float* Wv    = (const float*)d_in[7];
    const float* bv    = (const float*)d_in[8];
    const float* Wf    = (const float*)d_in[9];
    const float* bf    = (const float*)d_in[10];
    float* out = (float*)d_out;

    // kbuf 16384 + vbuf 24576 + part 1024 + att_pk 512 + c 16 floats
    const int k3_smem = (16384 + 24576 + 1024 + 512 + 16) * 4;   // 170048 B
    static bool attr_set = false;
    if (!attr_set) {
        cudaFuncSetAttribute(k3_fused, cudaFuncAttributeMaxDynamicSharedMemorySize, k3_smem);
        attr_set = true;
    }

    k1_q<<<(BATCH * HDIM * 32 + 255) / 256, 256>>>(query, Wq, bq);
    k2_w<<<HN * BATCH, 256>>>(Wk, bk);
    {
        dim3 grid(SEQ / 512, BATCH);   // 8 x 16 = 128 CTAs, single wave
        k3_fused<<<grid, 512, k3_smem>>>(key_, value);
    }
    k4_out<<<(HDIM * BATCH * 32 + 255) / 256, 256>>>(Wv, bv);
    k5_final<<<(HDIM * BATCH * 32 + 255) / 256, 256>>>(Wf, bf, out);
}

// round 9
// speedup vs baseline: 1.2533x; 1.0692x over previous
#include <cuda_runtime.h>
#include <cuda_bf16.h>

// Problem constants
#define BATCH 16
#define SEQ   4096
#define HDIM  1024
#define HN    16      // heads
#define HD    64      // head dim

// ---------------------------------------------------------------------------
// Scratch (device globals: no allocation allowed)
// ---------------------------------------------------------------------------
__device__ float g_q[BATCH * HDIM];          // q = query @ Wq^T + bq
__device__ float g_wt[BATCH * HDIM * HN];    // wT[b][k][h] = (1/32) Wk_h^T q_h, tf32-rounded
__device__ float g_c[BATCH * HN];            // (1/32) q_h . bk_h
__device__ float g_att[BATCH * SEQ * HN];    // softmax attention [b,s,h]
__device__ float g_u[BATCH * HN * HDIM];     // u[b,h,:] = sum_s att * value_row
__device__ float g_A[BATCH * HN];            // A[b,h]   = sum_s att
__device__ float g_o1[BATCH * HDIM];         // out before final projection

// ---------------------------------------------------------------------------
// helpers
// ---------------------------------------------------------------------------
__device__ __forceinline__ void fma2(unsigned long long &d,
                                     unsigned long long a,
                                     unsigned long long b) {
    asm("fma.rn.f32x2 %0, %1, %2, %0;" : "+l"(d) : "l"(a), "l"(b));
}
__device__ __forceinline__ float2 unpack2(unsigned long long v) {
    float2 f;
    asm("mov.b64 {%0, %1}, %2;" : "=f"(f.x), "=f"(f.y) : "l"(v));
    return f;
}
__device__ __forceinline__ unsigned long long pack_dup(float a) {
    unsigned long long r;
    asm("mov.b64 %0, {%1, %1};" : "=l"(r) : "f"(a));
    return r;
}
__device__ __forceinline__ unsigned smem_u32(const void* p) {
    unsigned a;
    asm("{ .reg .u64 t; cvta.to.shared.u64 t, %1; cvt.u32.u64 %0, t; }"
        : "=r"(a) : "l"(p));
    return a;
}
__device__ __forceinline__ void cp_async16(unsigned dst, const void* src) {
    asm volatile("cp.async.cg.shared.global [%0], [%1], 16;"
                 :: "r"(dst), "l"(src) : "memory");
}
__device__ __forceinline__ void cp_commit() {
    asm volatile("cp.async.commit_group;" ::: "memory");
}
__device__ __forceinline__ void cp_wait1() {
    asm volatile("cp.async.wait_group 1;" ::: "memory");
}
__device__ __forceinline__ void cp_wait2() {
    asm volatile("cp.async.wait_group 2;" ::: "memory");
}
__device__ __forceinline__ unsigned f2tf32(float f) {
    unsigned r;
    asm("cvt.rna.tf32.f32 %0, %1;" : "=r"(r) : "f"(f));
    return r;
}
// mma.sync m16n8k8 tf32: D += A(16x8) * B(8x8)
__device__ __forceinline__ void mma_tf32(float* d, unsigned a0, unsigned a1,
                                         unsigned a2, unsigned a3,
                                         unsigned b0, unsigned b1) {
    asm("mma.sync.aligned.m16n8k8.row.col.f32.tf32.tf32.f32 "
        "{%0,%1,%2,%3}, {%4,%5,%6,%7}, {%8,%9}, {%0,%1,%2,%3};"
        : "+f"(d[0]), "+f"(d[1]), "+f"(d[2]), "+f"(d[3])
        : "r"(a0), "r"(a1), "r"(a2), "r"(a3), "r"(b0), "r"(b1));
}

// ---------------------------------------------------------------------------
// K1: q[b,i] = query[b,:] . Wq[i,:] + bq[i]   (warp per output)
// ---------------------------------------------------------------------------
__global__ void k1_q(const float* __restrict__ query,
                     const float* __restrict__ Wq,
                     const float* __restrict__ bq) {
    int gw   = (blockIdx.x * blockDim.x + threadIdx.x) >> 5;
    int lane = threadIdx.x & 31;
    if (gw >= BATCH * HDIM) return;
    int b = gw >> 10, i = gw & 1023;
    const float4* qr = (const float4*)(query + b * HDIM);
    const float4* wr = (const float4*)(Wq + (size_t)i * HDIM);
    float acc = 0.f;
#pragma unroll
    for (int t = 0; t < 8; t++) {
        float4 a = qr[t * 32 + lane];
        float4 w = wr[t * 32 + lane];
        acc += a.x * w.x + a.y * w.y + a.z * w.z + a.w * w.w;
    }
#pragma unroll
    for (int o = 16; o > 0; o >>= 1) acc += __shfl_xor_sync(~0u, acc, o);
    if (lane == 0) g_q[gw] = acc + bq[i];
}

// ---------------------------------------------------------------------------
// K2: wT[b][j][h] = tf32( (1/32) sum_d q[b,h*64+d] * Wk[h*64+d, j] )
//     also zeros g_u/g_A.  block per (h,b), 256 threads.
// ---------------------------------------------------------------------------
__global__ void k2_w(const float* __restrict__ Wk,
                     const float* __restrict__ bk) {
    int h = blockIdx.x >> 4;
    int b = blockIdx.x & 15;
    int tid = threadIdx.x;

    int gtid = blockIdx.x * 256 + tid;
    ((float4*)g_u)[gtid] = make_float4(0.f, 0.f, 0.f, 0.f);
    if (gtid < BATCH * HN) g_A[gtid] = 0.f;

    __shared__ float qh[HD];
    if (tid < HD) qh[tid] = g_q[b * HDIM + h * HD + tid];
    __syncthreads();

    float4 acc = make_float4(0.f, 0.f, 0.f, 0.f);
    const float4* wk = (const float4*)(Wk + (size_t)(h * HD) * HDIM) + tid;
#pragma unroll 8
    for (int d = 0; d < HD; d++) {
        float4 v = wk[d * 256];
        float  s = qh[d];
        acc.x += s * v.x; acc.y += s * v.y; acc.z += s * v.z; acc.w += s * v.w;
    }
    const float scale = 0.03125f;  // 1/sqrt(1024)
    // store transposed, tf32-rounded: g_wt[(b*1024 + j)*16 + h], j = tid*4+jj
    float* wrow = g_wt + ((size_t)b * HDIM + tid * 4) * HN + h;
    wrow[0 * HN] = __uint_as_float(f2tf32(acc.x * scale));
    wrow[1 * HN] = __uint_as_float(f2tf32(acc.y * scale));
    wrow[2 * HN] = __uint_as_float(f2tf32(acc.z * scale));
    wrow[3 * HN] = __uint_as_float(f2tf32(acc.w * scale));

    if (tid == 0) {
        float cc = 0.f;
        for (int d = 0; d < HD; d++) cc += qh[d] * bk[h * HD + d];
        g_c[b * HN + h] = cc * scale;
    }
}

// ---------------------------------------------------------------------------
// K3a TENSOR: scores[128,16] per CTA via mma.m16n8k8.tf32, then softmax.
//  grid (32 chunks of 128 rows, 16 b), 256 thr (8 warps), 2 CTA/SM.
//  Warp w owns rows [w*16, w*16+16), all 16 heads (2 n-tiles).
//  K=1024 split into 16 chunks of 64; key chunk (32KB) + w chunk (6KB)
//  double-buffered via cp.async. D accumulators: 8 regs/thread.
//  ktile row stride 68 floats / wtile row stride 24 -> conflict-free frags.
// ---------------------------------------------------------------------------
#define KTS 68    // ktile row stride (floats)
#define WTS 24    // wtile row stride (floats)
__global__ __launch_bounds__(256, 2)
void k3a_scores(const float* __restrict__ key) {
    extern __shared__ float sm[];
    float* kt   = sm;                        // 2 x 128 x 68
    float* wt   = kt + 2 * 128 * KTS;        // 2 x 64 x 24
    float* scor = wt + 2 * 64 * WTS;         // 128 x 17
    float* c_s  = scor + 128 * 17;           // 16

    const int b    = blockIdx.y;
    const int rblk = blockIdx.x;
    const int row0 = rblk * 128;
    const int tid  = threadIdx.x;
    const int w    = tid >> 5;
    const int l    = tid & 31;
    const int g    = l >> 2;       // 0..7
    const int t4   = l & 3;        // 0..3

    if (tid < HN) c_s[tid] = g_c[b * HN + tid];

    const float* keyb = key + ((size_t)b * SEQ + row0) * HDIM;
    const float* wtb  = g_wt + (size_t)b * HDIM * HN;
    const unsigned kt_a = smem_u32(kt);
    const unsigned wt_a = smem_u32(wt);

    // chunk loader: key 128x64 f32 (2048 cp16) + w 64x16 (256 cp16)
    auto load_chunk = [&](int ch, int buf) {
        const int krow = tid >> 1;                 // 0..127
        const int s0   = (tid & 1) * 8;
        const float* srow = keyb + (size_t)krow * HDIM + ch * 64;
        const unsigned drow = kt_a + (buf * 128 * KTS + krow * KTS) * 4;
#pragma unroll
        for (int i = 0; i < 8; i++)
            cp_async16(drow + (s0 + i) * 16, srow + (s0 + i) * 4);
        const int wr = tid >> 2, sg = tid & 3;     // wr 0..63
        cp_async16(wt_a + (buf * 64 * WTS + wr * WTS + sg * 4) * 4,
                   wtb + (size_t)(ch * 64 + wr) * HN + sg * 4);
    };

    load_chunk(0, 0);
    cp_commit();

    float d[2][4] = {{0.f, 0.f, 0.f, 0.f}, {0.f, 0.f, 0.f, 0.f}};

    for (int ch = 0; ch < 16; ch++) {
        const int buf = ch & 1;
        if (ch + 1 < 16) load_chunk(ch + 1, buf ^ 1);
        cp_commit();
        cp_wait1();
        __syncthreads();

        const float* kbase = kt + buf * 128 * KTS + (w * 16 + g) * KTS + t4;
        const float* wbase = wt + buf * 64 * WTS;
#pragma unroll
        for (int kk = 0; kk < 8; kk++) {
            // A fragment (key rows, row-major)
            unsigned a0 = f2tf32(kbase[kk * 8]);
            unsigned a1 = f2tf32(kbase[8 * KTS + kk * 8]);
            unsigned a2 = f2tf32(kbase[kk * 8 + 4]);
            unsigned a3 = f2tf32(kbase[8 * KTS + kk * 8 + 4]);
            // B fragments (w, k-major), already tf32 bits
#pragma unroll
            for (int nt = 0; nt < 2; nt++) {
                unsigned b0 = __float_as_uint(wbase[(kk * 8 + t4) * WTS + nt * 8 + g]);
                unsigned b1 = __float_as_uint(wbase[(kk * 8 + t4 + 4) * WTS + nt * 8 + g]);
                mma_tf32(d[nt], a0, a1, a2, a3, b0, b1);
            }
        }
        __syncthreads();
    }

    // write D to scor[row][head]
#pragma unroll
    for (int nt = 0; nt < 2; nt++) {
        scor[(w * 16 + g) * 17 + nt * 8 + t4 * 2 + 0] = d[nt][0];
        scor[(w * 16 + g) * 17 + nt * 8 + t4 * 2 + 1] = d[nt][1];
        scor[(w * 16 + g + 8) * 17 + nt * 8 + t4 * 2 + 0] = d[nt][2];
        scor[(w * 16 + g + 8) * 17 + nt * 8 + t4 * 2 + 1] = d[nt][3];
    }
    __syncthreads();

    // softmax over heads + att store
    float* attb = g_att + ((size_t)b * SEQ + row0) * HN;
#pragma unroll
    for (int it = 0; it < 8; it++) {
        const int row = it * 16 + (tid >> 4);
        const int hh  = tid & 15;
        float sc = scor[row * 17 + hh] + c_s[hh];
        float m = sc;
#pragma unroll
        for (int o = 8; o > 0; o >>= 1) m = fmaxf(m, __shfl_xor_sync(~0u, m, o));
        float e = __expf(sc - m);
        float sum = e;
#pragma unroll
        for (int o = 8; o > 0; o >>= 1) sum += __shfl_xor_sync(~0u, sum, o);
        attb[row * HN + hh] = __fdividef(e, sum);
    }
}

// ---------------------------------------------------------------------------
// K3b: u[b,h,j] += sum_s att[b,s,h] * value[b,s,j]   (proven R4 version)
//  grid (16 chunks, 16 b), 256 thr, 2 CTA/SM.
// ---------------------------------------------------------------------------
__global__ __launch_bounds__(256, 2)
void k3b_accum(const float* __restrict__ value) {
    __shared__ unsigned long long att_s[512];   // 32 rows x 16 heads, packed {a,a}

    const int b = blockIdx.y;
    const int chunk = blockIdx.x;
    const int tid = threadIdx.x;
    const int wq = tid >> 5;
    const int lane = tid & 31;
    const int j0 = (wq << 7) + (lane << 2);

    const float* valb = value + (size_t)b * SEQ * HDIM;
    const float* attb = g_att + (size_t)b * SEQ * HN;
    const int row0 = chunk << 8;

    unsigned long long u2[32];
#pragma unroll
    for (int i = 0; i < 32; i++) u2[i] = 0ULL;
    float a_loc = 0.f;

    for (int G = 0; G < 8; G++) {
        const int r32 = row0 + G * 32;
        {
            const float* asrc = attb + (size_t)r32 * HN;
            att_s[tid]       = pack_dup(asrc[tid]);
            att_s[tid + 256] = pack_dup(asrc[tid + 256]);
        }
        __syncthreads();

#pragma unroll
        for (int g4 = 0; g4 < 4; g4++) {
            const int rb = r32 + g4 * 8;
            ulonglong2 vv[8];
#pragma unroll
            for (int r = 0; r < 8; r++)
                vv[r] = *(const ulonglong2*)(valb + (size_t)(rb + r) * HDIM + j0);
#pragma unroll
            for (int r = 0; r < 8; r++) {
#pragma unroll
                for (int h = 0; h < 16; h++) {
                    unsigned long long a2 = att_s[(g4 * 8 + r) * 16 + h];
                    fma2(u2[2 * h + 0], a2, vv[r].x);
                    fma2(u2[2 * h + 1], a2, vv[r].y);
                }
            }
        }
        if (tid < 16) {
#pragma unroll
            for (int r = 0; r < 32; r++)
                a_loc += ((const float*)att_s)[(r * 16 + tid) * 2];
        }
        __syncthreads();
    }

    float* ubase = g_u + (b * HN) * HDIM + j0;
#pragma unroll
    for (int h = 0; h < 16; h++) {
        float2 lo = unpack2(u2[2 * h + 0]);
        float2 hi = unpack2(u2[2 * h + 1]);
        atomicAdd(ubase + (h << 10) + 0, lo.x);
        atomicAdd(ubase + (h << 10) + 1, lo.y);
        atomicAdd(ubase + (h << 10) + 2, hi.x);
        atomicAdd(ubase + (h << 10) + 3, hi.y);
    }
    if (tid < 16) atomicAdd(&g_A[b * HN + tid], a_loc);
}

// ---------------------------------------------------------------------------
// K4: o1[b,j] = Wv[j,:] . u[b, j/64, :] + bv[j] * A[b, j/64]   warp per (j,b)
// ---------------------------------------------------------------------------
__global__ void k4_out(const float* __restrict__ Wv,
                       const float* __restrict__ bv) {
    int gw   = (blockIdx.x * blockDim.x + threadIdx.x) >> 5;
    int lane = threadIdx.x & 31;
    if (gw >= HDIM * BATCH) return;
    int b = gw & 15, j = gw >> 4, h = j >> 6;
    const float4* wr = (const float4*)(Wv + (size_t)j * HDIM);
    const float4* ur = (const float4*)(g_u + (b * HN + h) * HDIM);
    float acc = 0.f;
#pragma unroll
    for (int t = 0; t < 8; t++) {
        float4 w = wr[t * 32 + lane];
        float4 u = ur[t * 32 + lane];
        acc += w.x * u.x + w.y * u.y + w.z * u.z + w.w * u.w;
    }
#pragma unroll
    for (int o = 16; o > 0; o >>= 1) acc += __shfl_xor_sync(~0u, acc, o);
    if (lane == 0) g_o1[b * HDIM + j] = acc + bv[j] * g_A[b * HN + h];
}

// ---------------------------------------------------------------------------
// K5: res[b,i] = Wf[i,:] . o1[b,:] + bf[i]   warp per (i,b)
// ---------------------------------------------------------------------------
__global__ void k5_final(const float* __restrict__ Wf,
                         const float* __restrict__ bf,
                         float* __restrict__ res) {
    int gw   = (blockIdx.x * blockDim.x + threadIdx.x) >> 5;
    int lane = threadIdx.x & 31;
    if (gw >= HDIM * BATCH) return;
    int b = gw & 15, i = gw >> 4;
    const float4* wr = (const float4*)(Wf + (size_t)i * HDIM);
    const float4* orow = (const float4*)(g_o1 + b * HDIM);
    float acc = 0.f;
#pragma unroll
    for (int t = 0; t < 8; t++) {
        float4 w = wr[t * 32 + lane];
        float4 o = orow[t * 32 + lane];
        acc += w.x * o.x + w.y * o.y + w.z * o.z + w.w * o.w;
    }
#pragma unroll
    for (int o = 16; o > 0; o >>= 1) acc += __shfl_xor_sync(~0u, acc, o);
    if (lane == 0) res[b * HDIM + i] = acc + bf[i];
}

// ---------------------------------------------------------------------------
// launch
// ---------------------------------------------------------------------------
extern "C" void kernel_launch(void* const* d_in, const int* in_sizes, int n_in,
                              void* d_out, int out_size) {
    const float* query = (const float*)d_in[0];
    const float* key_  = (const float*)d_in[1];
    const float* value = (const float*)d_in[2];
    const float* Wq    = (const float*)d_in[3];
    const float* bq    = (const float*)d_in[4];
    const float* Wk    = (const float*)d_in[5];
    const float* bk    = (const float*)d_in[6];
    const float* Wv    = (const float*)d_in[7];
    const float* bv    = (const float*)d_in[8];
    const float* Wf    = (const float*)d_in[9];
    const float* bf    = (const float*)d_in[10];
    float* out = (float*)d_out;

    // kt 2*128*68 + wt 2*64*24 + scor 128*17 + c 16  floats
    const int k3a_smem = (2 * 128 * KTS + 2 * 64 * WTS + 128 * 17 + 16) * 4;  // 90688 B
    static bool attr_set = false;
    if (!attr_set) {
        cudaFuncSetAttribute(k3a_scores, cudaFuncAttributeMaxDynamicSharedMemorySize, k3a_smem);
        attr_set = true;
    }

    k1_q<<<(BATCH * HDIM * 32 + 255) / 256, 256>>>(query, Wq, bq);
    k2_w<<<HN * BATCH, 256>>>(Wk, bk);
    {
        dim3 grid_a(SEQ / 128, BATCH);
        k3a_scores<<<grid_a, 256, k3a_smem>>>(key_);
        dim3 grid_b(SEQ / 256, BATCH);
        k3b_accum<<<grid_b, 256>>>(value);
    }
    k4_out<<<(HDIM * BATCH * 32 + 255) / 256, 256>>>(Wv, bv);
    k5_final<<<(HDIM * BATCH * 32 + 255) / 256, 256>>>(Wf, bf, out);
}